// round 14
// baseline (speedup 1.0000x reference)
#include <cuda_runtime.h>
#include <cstdint>

#define B 64
#define S 128
#define E 512
#define H 512
#define A 256
#define V 8192
#define T 32
#define HE 1024   /* H + E */
#define G4 2048   /* 4*H   */
#define KX 1536   /* H + E + H : gates GEMM K */
#define PADK 40

typedef unsigned long long ull;

// ---------------- persistent device scratch (no allocations allowed) -------
__device__ float g_enc_proj[B * S * A];
__device__ float g_scores[B * S];
__device__ __align__(16) unsigned short g_histH[T * B * HE];  // [t*B+b][ h | ctx ]
__device__ __align__(16) unsigned short g_histL[T * B * HE];
__device__ __align__(16) unsigned short g_WoutH[V * HE];
__device__ __align__(16) unsigned short g_WoutL[V * HE];
__device__ __align__(16) unsigned short g_encH[B * S * E];
__device__ __align__(16) unsigned short g_encL[B * S * E];
__device__ __align__(16) unsigned short g_WencH[A * E];
__device__ __align__(16) unsigned short g_WencL[A * E];
__device__ __align__(16) unsigned short g_WgH[G4 * KX];
__device__ __align__(16) unsigned short g_WgL[G4 * KX];
__device__ __align__(16) unsigned short g_WdecTH[A * H];  // [a][k]
__device__ __align__(16) unsigned short g_WdecTL[A * H];
__device__ __align__(16) unsigned short g_xhH[B * KX];   // [b][ xemb | ctx | h ]
__device__ __align__(16) unsigned short g_xhL[B * KX];
__device__ float g_dec[B * A];
__device__ float g_c[B * H];
__device__ float g_gates[B * G4];
__device__ float g_bias[G4];

// ---------------- helpers --------------------------------------------------
__device__ __forceinline__ float fast_tanh(float x) {
    float r; asm("tanh.approx.f32 %0, %1;" : "=f"(r) : "f"(x)); return r;
}
__device__ __forceinline__ unsigned packhl(float x0, float x1, unsigned& lo_out) {
    unsigned hi;
    asm("cvt.rn.bf16x2.f32 %0, %1, %2;" : "=r"(hi) : "f"(x1), "f"(x0));
    float h0 = __uint_as_float(hi << 16);
    float h1 = __uint_as_float(hi & 0xffff0000u);
    float l0 = x0 - h0, l1 = x1 - h1;
    asm("cvt.rn.bf16x2.f32 %0, %1, %2;" : "=r"(lo_out) : "f"(l1), "f"(l0));
    return hi;
}
__device__ __forceinline__ void mma16816(float* c, uint32_t a0, uint32_t a1,
                                         uint32_t a2, uint32_t a3,
                                         uint32_t b0, uint32_t b1) {
    asm volatile(
        "mma.sync.aligned.m16n8k16.row.col.f32.bf16.bf16.f32 "
        "{%0,%1,%2,%3}, {%4,%5,%6,%7}, {%8,%9}, {%0,%1,%2,%3};"
        : "+f"(c[0]), "+f"(c[1]), "+f"(c[2]), "+f"(c[3])
        : "r"(a0), "r"(a1), "r"(a2), "r"(a3), "r"(b0), "r"(b1));
}
__device__ __forceinline__ void cpa16(unsigned saddr, const void* g) {
    asm volatile("cp.async.ca.shared.global [%0], [%1], 16;" :: "r"(saddr), "l"(g));
}
#define CP_COMMIT() asm volatile("cp.async.commit_group;")
#define CP_WAIT1()  asm volatile("cp.async.wait_group 1;")
#define CP_WAIT0()  asm volatile("cp.async.wait_group 0;")
__device__ __forceinline__ unsigned smem_u32(const void* p) {
    unsigned r;
    asm("{ .reg .u64 t; cvta.to.shared.u64 t, %1; cvt.u32.u64 %0, t; }"
        : "=r"(r) : "l"(p));
    return r;
}

// ---------------- init ------------------------------------------------------
__global__ void k_init(const float* __restrict__ b_ih, const float* __restrict__ b_hh) {
    int idx = blockIdx.x * 256 + threadIdx.x;   // 32768
    if (idx < B * H) g_c[idx] = 0.f;
    if (idx < G4) g_bias[idx] = b_ih[idx] + b_hh[idx];
    {
        int b = idx >> 9, j = idx & 511;
        g_xhH[b * KX + 1024 + j] = 0;
        g_xhL[b * KX + 1024 + j] = 0;
    }
}

// ---------------- merged conversion/pack kernel -----------------------------
// regions (blocks): enc 8192 | Wout 16384 | WencT 256 | Wg 6144 | WdecT 256
__global__ void k_pack(const float* __restrict__ enc, const float* __restrict__ Wout,
                       const float* __restrict__ Wenc, const float* __restrict__ Wih,
                       const float* __restrict__ Whh, const float* __restrict__ Wdec) {
    int blk = blockIdx.x, tid = threadIdx.x;
    if (blk < 8192) {
        int i = (blk * 256 + tid) * 2;
        float2 f = *(const float2*)&enc[i];
        unsigned lo, hi = packhl(f.x, f.y, lo);
        *(unsigned*)&g_encH[i] = hi;
        *(unsigned*)&g_encL[i] = lo;
    } else if (blk < 8192 + 16384) {
        int i = ((blk - 8192) * 256 + tid) * 2;
        float2 f = *(const float2*)&Wout[i];
        unsigned lo, hi = packhl(f.x, f.y, lo);
        *(unsigned*)&g_WoutH[i] = hi;
        *(unsigned*)&g_WoutL[i] = lo;
    } else if (blk < 8192 + 16384 + 256) {
        int i = ((blk - 8192 - 16384) * 256 + tid) * 2;
        int a = i >> 9, k = i & 511;
        float x0 = Wenc[k * A + a];
        float x1 = Wenc[(k + 1) * A + a];
        unsigned lo, hi = packhl(x0, x1, lo);
        *(unsigned*)&g_WencH[i] = hi;
        *(unsigned*)&g_WencL[i] = lo;
    } else if (blk < 8192 + 16384 + 256 + 6144) {
        int i = ((blk - 8192 - 16384 - 256) * 256 + tid) * 2;
        int n = i / KX, k = i % KX;
        float x0 = (k < HE) ? Wih[n * HE + k] : Whh[n * H + (k - HE)];
        float x1 = (k + 1 < HE) ? Wih[n * HE + k + 1] : Whh[n * H + (k + 1 - HE)];
        unsigned lo, hi = packhl(x0, x1, lo);
        *(unsigned*)&g_WgH[i] = hi;
        *(unsigned*)&g_WgL[i] = lo;
    } else {                                    // WdecT [a][k] from Wdec[k][a]
        int i = ((blk - 8192 - 16384 - 256 - 6144) * 256 + tid) * 2;
        int a = i >> 9, k = i & 511;
        float x0 = Wdec[k * A + a];
        float x1 = Wdec[(k + 1) * A + a];
        unsigned lo, hi = packhl(x0, x1, lo);
        *(unsigned*)&g_WdecTH[i] = hi;
        *(unsigned*)&g_WdecTL[i] = lo;
    }
}

// ---------------- per-step: LSTM(t-1) + h pack + zero gates + seed dec -----
__global__ void __launch_bounds__(512) k_lstmA(const float* __restrict__ b_att, int t) {
    int b = blockIdx.x, tid = threadIdx.x;
    if (t > 0) {
        const float* gr = &g_gates[b * G4];
        float gi = gr[tid]         + g_bias[tid];
        float gf = gr[tid + 512]   + g_bias[tid + 512];
        float gg = gr[tid + 1024]  + g_bias[tid + 1024];
        float go = gr[tid + 1536]  + g_bias[tid + 1536];
        float si = 1.f / (1.f + expf(-gi));
        float sf = 1.f / (1.f + expf(-gf));
        float so = 1.f / (1.f + expf(-go));
        float c  = sf * g_c[b * H + tid] + si * tanhf(gg);
        float hn = so * tanhf(c);
        g_c[b * H + tid] = c;
        float hp = __shfl_xor_sync(0xffffffffu, hn, 1);
        if (!(tid & 1)) {
            unsigned lo, hi = packhl(hn, hp, lo);
            *(unsigned*)&g_xhH[b * KX + 1024 + tid] = hi;
            *(unsigned*)&g_xhL[b * KX + 1024 + tid] = lo;
            *(unsigned*)&g_histH[((t - 1) * B + b) * HE + tid] = hi;
            *(unsigned*)&g_histL[((t - 1) * B + b) * HE + tid] = lo;
        }
    }
    if (t >= T) return;
    *(float4*)&g_gates[b * G4 + tid * 4] = make_float4(0.f, 0.f, 0.f, 0.f);
    if (tid < A) g_dec[b * A + tid] = b_att[tid];   // seed for dec-GEMM atomics
}

// ---------------- generic M=64 mma GEMM (gates / dec), cp.async 2-stage ----
// A = g_xh (ld KX, k-offset aoff); C += A@Bw^T via atomics. grid (ntiles, ksplit)
#define MG_STG 15360
__global__ void __launch_bounds__(256) k_mgen(
    int aoff, const unsigned short* __restrict__ Bh,
    const unsigned short* __restrict__ Bl, int ldb, int nkc, int nsplit,
    float* __restrict__ C, int ldc)
{
    extern __shared__ __align__(16) unsigned short dsm[];
    int tid = threadIdx.x, warp = tid >> 5, lane = tid & 31;
    int N0 = blockIdx.x * 128;
    int wr = warp >> 2, wc = warp & 3;
    unsigned sb = smem_u32(dsm);
    float acc[2][4][4];
#pragma unroll
    for (int i = 0; i < 2; i++)
#pragma unroll
        for (int j = 0; j < 4; j++)
#pragma unroll
            for (int q = 0; q < 4; q++) acc[i][j][q] = 0.f;

    int cr = tid >> 1, ch = (tid & 1) * 16;
    auto load_stage = [&](int kc, int st) {
        int k0 = kc * 32;
        unsigned base = sb + st * (MG_STG * 2);
        if (tid < 128) {
            const unsigned short* pa = g_xhH + cr * KX + aoff + k0 + ch;
            const unsigned short* pl = g_xhL + cr * KX + aoff + k0 + ch;
            unsigned so = base + (cr * PADK + ch) * 2;
            cpa16(so, pa);             cpa16(so + 16, pa + 8);
            cpa16(so + 2560 * 2, pl);  cpa16(so + 2560 * 2 + 16, pl + 8);
        }
        {
            const unsigned short* pb = Bh + (size_t)(N0 + cr) * ldb + k0 + ch;
            const unsigned short* pbl= Bl + (size_t)(N0 + cr) * ldb + k0 + ch;
            unsigned so = base + (5120 + cr * PADK + ch) * 2;
            cpa16(so, pb);             cpa16(so + 16, pb + 8);
            cpa16(so + 5120 * 2, pbl); cpa16(so + 5120 * 2 + 16, pbl + 8);
        }
        CP_COMMIT();
    };

    int kc0 = blockIdx.y;
    load_stage(kc0, 0);
    int st = 0;
    for (int kc = kc0; kc < nkc; kc += nsplit) {
        if (kc + nsplit < nkc) { load_stage(kc + nsplit, st ^ 1); CP_WAIT1(); }
        else CP_WAIT0();
        __syncthreads();
        unsigned short* sAh = dsm + st * MG_STG;
        unsigned short* sAl = sAh + 2560;
        unsigned short* sBh = sAh + 5120;
        unsigned short* sBl = sAh + 10240;
#pragma unroll
        for (int kq = 0; kq < 2; kq++) {
            int kb = kq * 16 + (lane & 3) * 2;
            uint32_t ah[2][4], al[2][4], bh[4][2], bl[4][2];
#pragma unroll
            for (int mf = 0; mf < 2; mf++) {
                int r = wr * 32 + mf * 16 + (lane >> 2);
                ah[mf][0] = *(const uint32_t*)&sAh[r * PADK + kb];
                ah[mf][1] = *(const uint32_t*)&sAh[(r + 8) * PADK + kb];
                ah[mf][2] = *(const uint32_t*)&sAh[r * PADK + kb + 8];
                ah[mf][3] = *(const uint32_t*)&sAh[(r + 8) * PADK + kb + 8];
                al[mf][0] = *(const uint32_t*)&sAl[r * PADK + kb];
                al[mf][1] = *(const uint32_t*)&sAl[(r + 8) * PADK + kb];
                al[mf][2] = *(const uint32_t*)&sAl[r * PADK + kb + 8];
                al[mf][3] = *(const uint32_t*)&sAl[(r + 8) * PADK + kb + 8];
            }
#pragma unroll
            for (int nf = 0; nf < 4; nf++) {
                int r = wc * 32 + nf * 8 + (lane >> 2);
                bh[nf][0] = *(const uint32_t*)&sBh[r * PADK + kb];
                bh[nf][1] = *(const uint32_t*)&sBh[r * PADK + kb + 8];
                bl[nf][0] = *(const uint32_t*)&sBl[r * PADK + kb];
                bl[nf][1] = *(const uint32_t*)&sBl[r * PADK + kb + 8];
            }
#pragma unroll
            for (int mf = 0; mf < 2; mf++)
#pragma unroll
                for (int nf = 0; nf < 4; nf++) {
                    mma16816(acc[mf][nf], ah[mf][0], ah[mf][1], ah[mf][2], ah[mf][3],
                             bh[nf][0], bh[nf][1]);
                    mma16816(acc[mf][nf], al[mf][0], al[mf][1], al[mf][2], al[mf][3],
                             bh[nf][0], bh[nf][1]);
                    mma16816(acc[mf][nf], ah[mf][0], ah[mf][1], ah[mf][2], ah[mf][3],
                             bl[nf][0], bl[nf][1]);
                }
        }
        __syncthreads();
        st ^= 1;
    }
#pragma unroll
    for (int mf = 0; mf < 2; mf++) {
        int m = wr * 32 + mf * 16 + (lane >> 2);
#pragma unroll
        for (int nf = 0; nf < 4; nf++) {
            int n = N0 + wc * 32 + nf * 8 + (lane & 3) * 2;
            atomicAdd(&C[m * ldc + n],           acc[mf][nf][0]);
            atomicAdd(&C[m * ldc + n + 1],       acc[mf][nf][1]);
            atomicAdd(&C[(m + 8) * ldc + n],     acc[mf][nf][2]);
            atomicAdd(&C[(m + 8) * ldc + n + 1], acc[mf][nf][3]);
        }
    }
}

// ---------------- per-step: scores (grid (B,8), warp = 2 s-rows) -----------
__global__ void __launch_bounds__(256) k_score(const float* __restrict__ v_att) {
    __shared__ float sh_dec[A];
    __shared__ float sh_v[A];
    int b = blockIdx.x, sc = blockIdx.y, tid = threadIdx.x;
    sh_dec[tid] = g_dec[b * A + tid];
    sh_v[tid]   = v_att[tid];
    __syncthreads();
    int wid = tid >> 5, lane = tid & 31;
#pragma unroll
    for (int r = 0; r < 2; r++) {
        int s = sc * 16 + wid * 2 + r;
        const float* ep = &g_enc_proj[(b * S + s) * A];
        float p = 0.f;
#pragma unroll
        for (int q = 0; q < 8; q++) {
            int a = lane + 32 * q;
            p += fast_tanh(ep[a] + sh_dec[a]) * sh_v[a];
        }
#pragma unroll
        for (int off = 16; off; off >>= 1) p += __shfl_down_sync(0xffffffffu, p, off);
        if (lane == 0) g_scores[b * S + s] = p;
    }
}

// ---------------- per-step: softmax + ctx e-chunk + all packs --------------
// grid (B, 4); softmax recomputed per block (cheap).
__global__ void __launch_bounds__(256) k_ctx(const float* __restrict__ enc,
                                             const int* __restrict__ tgt,
                                             const float* __restrict__ emb, int t) {
    __shared__ float sw[S];
    __shared__ float sacc[256];
    __shared__ float sred;
    int b = blockIdx.x, ec = blockIdx.y, tid = threadIdx.x;
    if (tid < S) sw[tid] = g_scores[b * S + tid];
    __syncthreads();
    if (tid < 32) {
        float m = fmaxf(fmaxf(sw[tid], sw[tid + 32]), fmaxf(sw[tid + 64], sw[tid + 96]));
#pragma unroll
        for (int off = 16; off; off >>= 1) m = fmaxf(m, __shfl_xor_sync(0xffffffffu, m, off));
        if (tid == 0) sred = m;
    }
    __syncthreads();
    float mx = sred;
    if (tid < S) sw[tid] = expf(sw[tid] - mx);
    __syncthreads();
    if (tid < 32) {
        float ssum = sw[tid] + sw[tid + 32] + sw[tid + 64] + sw[tid + 96];
#pragma unroll
        for (int off = 16; off; off >>= 1) ssum += __shfl_xor_sync(0xffffffffu, ssum, off);
        if (tid == 0) sred = 1.f / ssum;
    }
    __syncthreads();
    float rinv = sred;

    // ctx e-chunk: e = ec*128 + (tid&127), two threads per e over s-halves
    int ex = tid & 127, shalf = tid >> 7;
    float acc = 0.f;
    const float* eb = &enc[b * S * E + shalf * 64 * E + ec * 128 + ex];
#pragma unroll 8
    for (int s = 0; s < 64; s++)
        acc += sw[shalf * 64 + s] * eb[s * E];
    sacc[tid] = acc;
    __syncthreads();
    if (tid < 64) {
        float v0 = (sacc[2 * tid]     + sacc[2 * tid + 128]) * rinv;
        float v1 = (sacc[2 * tid + 1] + sacc[2 * tid + 129]) * rinv;
        unsigned lo, hi = packhl(v0, v1, lo);
        int off = 512 + ec * 128 + 2 * tid;   // xh ctx slot
        *(unsigned*)&g_xhH[b * KX + off] = hi;
        *(unsigned*)&g_xhL[b * KX + off] = lo;
        int hoff = (t * B + b) * HE + H + ec * 128 + 2 * tid;
        *(unsigned*)&g_histH[hoff] = hi;
        *(unsigned*)&g_histL[hoff] = lo;
    }
    // xemb pack (blocks ec 0/1 cover 512 elems)
    if (ec < 2 && tid < 128) {
        int tok = (t == 0) ? 0 : tgt[b * T + (t - 1)];
        float x0 = emb[tok * H + ec * 256 + 2 * tid];
        float x1 = emb[tok * H + ec * 256 + 2 * tid + 1];
        unsigned lo, hi = packhl(x0, x1, lo);
        *(unsigned*)&g_xhH[b * KX + ec * 256 + 2 * tid] = hi;
        *(unsigned*)&g_xhL[b * KX + ec * 256 + 2 * tid] = lo;
    }
}

// ---------------- 128x128 mma GEMM, cp.async double-buffered ---------------
#define MM_STG 20480
__global__ void __launch_bounds__(256) k_mma128(
    const unsigned short* __restrict__ Ahg, const unsigned short* __restrict__ Alg,
    const unsigned short* __restrict__ Bhg, const unsigned short* __restrict__ Blg,
    int ldk, int nkc, const float* __restrict__ bias,
    float* __restrict__ out, int ldc, int perm)
{
    extern __shared__ __align__(16) unsigned short dsm[];
    int tid = threadIdx.x, warp = tid >> 5, lane = tid & 31;
    int N0 = blockIdx.x * 128, M0 = blockIdx.y * 128;
    int wr = warp >> 2, wc = warp & 3;
    unsigned sb = smem_u32(dsm);
    float acc[4][4][4];
#pragma unroll
    for (int i = 0; i < 4; i++)
#pragma unroll
        for (int j = 0; j < 4; j++)
#pragma unroll
            for (int q = 0; q < 4; q++) acc[i][j][q] = 0.f;

    int cr = tid >> 1, ch = (tid & 1) * 16;
    auto load_stage = [&](int kc, int st) {
        int k0 = kc * 32;
        unsigned base = sb + st * (MM_STG * 2);
        unsigned so = base + (cr * PADK + ch) * 2;
        const unsigned short* pa = Ahg + (size_t)(M0 + cr) * ldk + k0 + ch;
        const unsigned short* pl = Alg + (size_t)(M0 + cr) * ldk + k0 + ch;
        const unsigned short* pb = Bhg + (size_t)(N0 + cr) * ldk + k0 + ch;
        const unsigned short* pbl= Blg + (size_t)(N0 + cr) * ldk + k0 + ch;
        cpa16(so, pa);                  cpa16(so + 16, pa + 8);
        cpa16(so + 5120 * 2, pl);       cpa16(so + 5120 * 2 + 16, pl + 8);
        cpa16(so + 10240 * 2, pb);      cpa16(so + 10240 * 2 + 16, pb + 8);
        cpa16(so + 15360 * 2, pbl);     cpa16(so + 15360 * 2 + 16, pbl + 8);
        CP_COMMIT();
    };

    load_stage(0, 0);
    int st = 0;
    for (int kc = 0; kc < nkc; kc++) {
        if (kc + 1 < nkc) { load_stage(kc + 1, st ^ 1); CP_WAIT1(); }
        else CP_WAIT0();
        __syncthreads();
        unsigned short* sAh = dsm + st * MM_STG;
        unsigned short* sAl = sAh + 5120;
        unsigned short* sBh = sAh + 10240;
        unsigned short* sBl = sAh + 15360;
#pragma unroll
        for (int kq = 0; kq < 2; kq++) {
            int kb = kq * 16 + (lane & 3) * 2;
            uint32_t ah[4][4], al[4][4], bh[4][2], bl[4][2];
            int ar = wr * 64 + (lane >> 2);
#pragma unroll
            for (int mf = 0; mf < 4; mf++) {
                int r = ar + mf * 16;
                ah[mf][0] = *(const uint32_t*)&sAh[r * PADK + kb];
                ah[mf][1] = *(const uint32_t*)&sAh[(r + 8) * PADK + kb];
                ah[mf][2] = *(const uint32_t*)&sAh[r * PADK + kb + 8];
                ah[mf][3] = *(const uint32_t*)&sAh[(r + 8) * PADK + kb + 8];
                al[mf][0] = *(const uint32_t*)&sAl[r * PADK + kb];
                al[mf][1] = *(const uint32_t*)&sAl[(r + 8) * PADK + kb];
                al[mf][2] = *(const uint32_t*)&sAl[r * PADK + kb + 8];
                al[mf][3] = *(const uint32_t*)&sAl[(r + 8) * PADK + kb + 8];
            }
            int br = wc * 32 + (lane >> 2);
#pragma unroll
            for (int nf = 0; nf < 4; nf++) {
                int r = br + nf * 8;
                bh[nf][0] = *(const uint32_t*)&sBh[r * PADK + kb];
                bh[nf][1] = *(const uint32_t*)&sBh[r * PADK + kb + 8];
                bl[nf][0] = *(const uint32_t*)&sBl[r * PADK + kb];
                bl[nf][1] = *(const uint32_t*)&sBl[r * PADK + kb + 8];
            }
#pragma unroll
            for (int mf = 0; mf < 4; mf++)
#pragma unroll
                for (int nf = 0; nf < 4; nf++) {
                    mma16816(acc[mf][nf], ah[mf][0], ah[mf][1], ah[mf][2], ah[mf][3],
                             bh[nf][0], bh[nf][1]);
                    mma16816(acc[mf][nf], al[mf][0], al[mf][1], al[mf][2], al[mf][3],
                             bh[nf][0], bh[nf][1]);
                    mma16816(acc[mf][nf], ah[mf][0], ah[mf][1], ah[mf][2], ah[mf][3],
                             bl[nf][0], bl[nf][1]);
                }
        }
        __syncthreads();
        st ^= 1;
    }
#pragma unroll
    for (int mf = 0; mf < 4; mf++) {
        int m0g = M0 + wr * 64 + mf * 16 + (lane >> 2);
#pragma unroll
        for (int nf = 0; nf < 4; nf++) {
            int n = N0 + wc * 32 + nf * 8 + (lane & 3) * 2;
            float2 bia = bias ? *(const float2*)&bias[n] : make_float2(0.f, 0.f);
            int m1 = m0g + 8;
            int r0 = perm ? ((m0g & 63) * T + (m0g >> 6)) : m0g;
            int r1 = perm ? ((m1 & 63) * T + (m1 >> 6)) : m1;
            float2 v0 = make_float2(acc[mf][nf][0] + bia.x, acc[mf][nf][1] + bia.y);
            float2 v1 = make_float2(acc[mf][nf][2] + bia.x, acc[mf][nf][3] + bia.y);
            *(float2*)&out[(size_t)r0 * ldc + n] = v0;
            *(float2*)&out[(size_t)r1 * ldc + n] = v1;
        }
    }
}

// ---------------- launch ----------------------------------------------------
extern "C" void kernel_launch(void* const* d_in, const int* in_sizes, int n_in,
                              void* d_out, int out_size) {
    const float* enc  = (const float*)d_in[0];
    const int*   tgt  = (const int*)  d_in[1];
    const float* emb  = (const float*)d_in[2];
    const float* Wenc = (const float*)d_in[3];
    const float* Wdec = (const float*)d_in[4];
    const float* batt = (const float*)d_in[5];
    const float* vatt = (const float*)d_in[6];
    const float* Wih  = (const float*)d_in[7];
    const float* Whh  = (const float*)d_in[8];
    const float* bih  = (const float*)d_in[9];
    const float* bhh  = (const float*)d_in[10];
    const float* Wout = (const float*)d_in[11];
    const float* bout = (const float*)d_in[12];
    float* out = (float*)d_out;

    float *encp, *decp, *gates;
    unsigned short *hH, *hL, *wH, *wL, *eH, *eL, *weH, *weL, *wgH, *wgL, *wdH, *wdL;
    cudaGetSymbolAddress((void**)&encp, g_enc_proj);
    cudaGetSymbolAddress((void**)&decp, g_dec);
    cudaGetSymbolAddress((void**)&gates, g_gates);
    cudaGetSymbolAddress((void**)&hH, g_histH);
    cudaGetSymbolAddress((void**)&hL, g_histL);
    cudaGetSymbolAddress((void**)&wH, g_WoutH);
    cudaGetSymbolAddress((void**)&wL, g_WoutL);
    cudaGetSymbolAddress((void**)&eH, g_encH);
    cudaGetSymbolAddress((void**)&eL, g_encL);
    cudaGetSymbolAddress((void**)&weH, g_WencH);
    cudaGetSymbolAddress((void**)&weL, g_WencL);
    cudaGetSymbolAddress((void**)&wgH, g_WgH);
    cudaGetSymbolAddress((void**)&wgL, g_WgL);
    cudaGetSymbolAddress((void**)&wdH, g_WdecTH);
    cudaGetSymbolAddress((void**)&wdL, g_WdecTL);

    static int attr_set = 0;
    if (!attr_set) {
        cudaFuncSetAttribute(k_mma128, cudaFuncAttributeMaxDynamicSharedMemorySize,
                             MM_STG * 4);
        cudaFuncSetAttribute(k_mgen, cudaFuncAttributeMaxDynamicSharedMemorySize,
                             MG_STG * 4);
        attr_set = 1;
    }

    k_init<<<128, 256>>>(bih, bhh);
    k_pack<<<8192 + 16384 + 256 + 6144 + 256, 256>>>(enc, Wout, Wenc, Wih, Whh, Wdec);
    k_mma128<<<dim3(A / 128, (B * S) / 128), 256, MM_STG * 4>>>(
        eH, eL, weH, weL, E, E / 32, nullptr, encp, A, 0);

    for (int t = 0; t < T; t++) {
        k_lstmA<<<B, 512>>>(batt, t);
        // dec += h@WdecT^T (seeded with b_att; A = xh h-part at offset 1024)
        k_mgen<<<dim3(2, 4), 256, MG_STG * 4>>>(1024, wdH, wdL, H, H / 32, 4,
                                                decp, A);
        k_score<<<dim3(B, 8), 256>>>(vatt);
        k_ctx<<<dim3(B, 4), 256>>>(enc, tgt, emb, t);
        // gates += xh@Wg^T (zeroed in k_lstmA)
        k_mgen<<<dim3(G4 / 128, 8), 256, MG_STG * 4>>>(0, wgH, wgL, KX, KX / 32, 8,
                                                       gates, G4);
    }
    k_lstmA<<<B, 512>>>(batt, T);   // final LSTM only

    // out = hist @ Wout^T + bout (permuted store to [B, T, V])
    k_mma128<<<dim3(V / 128, (T * B) / 128), 256, MM_STG * 4>>>(
        hH, hL, wH, wL, HE, HE / 32, bout, out, V, 1);
}

// round 17
// speedup vs baseline: 1.1210x; 1.1210x over previous
#include <cuda_runtime.h>
#include <cstdint>

#define B 64
#define S 128
#define E 512
#define H 512
#define A 256
#define V 8192
#define T 32
#define HE 1024   /* H + E */
#define G4 2048   /* 4*H   */
#define KX 1536   /* H + E + H : gates GEMM K */
#define PADK 40

typedef unsigned long long ull;

// ---------------- persistent device scratch (no allocations allowed) -------
__device__ float g_enc_proj[B * S * A];
__device__ __align__(16) unsigned short g_histH[T * B * HE];  // [t*B+b][ h | ctx ]
__device__ __align__(16) unsigned short g_histL[T * B * HE];
__device__ __align__(16) unsigned short g_WoutH[V * HE];
__device__ __align__(16) unsigned short g_WoutL[V * HE];
__device__ __align__(16) unsigned short g_encH[B * S * E];
__device__ __align__(16) unsigned short g_encL[B * S * E];
__device__ __align__(16) unsigned short g_WencH[A * E];
__device__ __align__(16) unsigned short g_WencL[A * E];
__device__ __align__(16) unsigned short g_WgH[G4 * KX];
__device__ __align__(16) unsigned short g_WgL[G4 * KX];
__device__ __align__(16) unsigned short g_xhH[B * KX];   // [b][ xemb | ctx | h ]
__device__ __align__(16) unsigned short g_xhL[B * KX];
__device__ float g_c[B * H];
__device__ float g_gates[B * G4];
__device__ float g_bias[G4];

// ---------------- helpers --------------------------------------------------
__device__ __forceinline__ float fast_tanh(float x) {
    float r; asm("tanh.approx.f32 %0, %1;" : "=f"(r) : "f"(x)); return r;
}
__device__ __forceinline__ unsigned packhl(float x0, float x1, unsigned& lo_out) {
    unsigned hi;
    asm("cvt.rn.bf16x2.f32 %0, %1, %2;" : "=r"(hi) : "f"(x1), "f"(x0));
    float h0 = __uint_as_float(hi << 16);
    float h1 = __uint_as_float(hi & 0xffff0000u);
    float l0 = x0 - h0, l1 = x1 - h1;
    asm("cvt.rn.bf16x2.f32 %0, %1, %2;" : "=r"(lo_out) : "f"(l1), "f"(l0));
    return hi;
}
__device__ __forceinline__ void mma16816(float* c, uint32_t a0, uint32_t a1,
                                         uint32_t a2, uint32_t a3,
                                         uint32_t b0, uint32_t b1) {
    asm volatile(
        "mma.sync.aligned.m16n8k16.row.col.f32.bf16.bf16.f32 "
        "{%0,%1,%2,%3}, {%4,%5,%6,%7}, {%8,%9}, {%0,%1,%2,%3};"
        : "+f"(c[0]), "+f"(c[1]), "+f"(c[2]), "+f"(c[3])
        : "r"(a0), "r"(a1), "r"(a2), "r"(a3), "r"(b0), "r"(b1));
}
__device__ __forceinline__ void cpa16(unsigned saddr, const void* g) {
    asm volatile("cp.async.ca.shared.global [%0], [%1], 16;" :: "r"(saddr), "l"(g));
}
#define CP_COMMIT() asm volatile("cp.async.commit_group;")
#define CP_WAIT1()  asm volatile("cp.async.wait_group 1;")
#define CP_WAIT0()  asm volatile("cp.async.wait_group 0;")
__device__ __forceinline__ unsigned smem_u32(const void* p) {
    unsigned r;
    asm("{ .reg .u64 t; cvta.to.shared.u64 t, %1; cvt.u32.u64 %0, t; }"
        : "=r"(r) : "l"(p));
    return r;
}

// ---------------- init ------------------------------------------------------
__global__ void k_init(const float* __restrict__ b_ih, const float* __restrict__ b_hh) {
    int idx = blockIdx.x * 256 + threadIdx.x;   // 32768
    if (idx < B * H) g_c[idx] = 0.f;
    if (idx < G4) g_bias[idx] = b_ih[idx] + b_hh[idx];
    {
        int b = idx >> 9, j = idx & 511;
        g_xhH[b * KX + 1024 + j] = 0;
        g_xhL[b * KX + 1024 + j] = 0;
    }
}

// ---------------- merged conversion/pack kernel -----------------------------
// regions (blocks): enc 8192 | Wout 16384 | WencT 256 | Wg 6144
__global__ void k_pack(const float* __restrict__ enc, const float* __restrict__ Wout,
                       const float* __restrict__ Wenc, const float* __restrict__ Wih,
                       const float* __restrict__ Whh) {
    int blk = blockIdx.x, tid = threadIdx.x;
    if (blk < 8192) {
        int i = (blk * 256 + tid) * 2;
        float2 f = *(const float2*)&enc[i];
        unsigned lo, hi = packhl(f.x, f.y, lo);
        *(unsigned*)&g_encH[i] = hi;
        *(unsigned*)&g_encL[i] = lo;
    } else if (blk < 8192 + 16384) {
        int i = ((blk - 8192) * 256 + tid) * 2;
        float2 f = *(const float2*)&Wout[i];
        unsigned lo, hi = packhl(f.x, f.y, lo);
        *(unsigned*)&g_WoutH[i] = hi;
        *(unsigned*)&g_WoutL[i] = lo;
    } else if (blk < 8192 + 16384 + 256) {
        int i = ((blk - 8192 - 16384) * 256 + tid) * 2;
        int a = i >> 9, k = i & 511;
        float x0 = Wenc[k * A + a];
        float x1 = Wenc[(k + 1) * A + a];
        unsigned lo, hi = packhl(x0, x1, lo);
        *(unsigned*)&g_WencH[i] = hi;
        *(unsigned*)&g_WencL[i] = lo;
    } else {
        int i = ((blk - 8192 - 16384 - 256) * 256 + tid) * 2;
        int n = i / KX, k = i % KX;
        float x0 = (k < HE) ? Wih[n * HE + k] : Whh[n * H + (k - HE)];
        float x1 = (k + 1 < HE) ? Wih[n * HE + k + 1] : Whh[n * H + (k + 1 - HE)];
        unsigned lo, hi = packhl(x0, x1, lo);
        *(unsigned*)&g_WgH[i] = hi;
        *(unsigned*)&g_WgL[i] = lo;
    }
}

// ---------------- per-step FUSED: LSTM(t-1) + dec + attention(t) -----------
// grid B, 512 threads. Internal phases restructured for MLP.
__global__ void __launch_bounds__(512) k_step(const float* __restrict__ v_att,
                                              const float* __restrict__ enc,
                                              const float* __restrict__ b_att,
                                              const float* __restrict__ Wdec,
                                              const int* __restrict__ tgt,
                                              const float* __restrict__ emb, int t) {
    __shared__ float sh[H];
    __shared__ __align__(16) float4 sred4[512];   // dec partial sums (8KB)
    __shared__ float sh_dec[A];
    __shared__ float sh_v[A];
    __shared__ float sw[S];
    __shared__ float sredv;
    int b = blockIdx.x, tid = threadIdx.x;
    int wid = tid >> 5, lane = tid & 31;

    // ---- LSTM for step t-1 ----
    if (t > 0) {
        const float* gr = &g_gates[b * G4];
        float gi = gr[tid]         + g_bias[tid];
        float gf = gr[tid + 512]   + g_bias[tid + 512];
        float gg = gr[tid + 1024]  + g_bias[tid + 1024];
        float go = gr[tid + 1536]  + g_bias[tid + 1536];
        float si = 1.f / (1.f + expf(-gi));
        float sf = 1.f / (1.f + expf(-gf));
        float so = 1.f / (1.f + expf(-go));
        float c  = sf * g_c[b * H + tid] + si * tanhf(gg);
        float hn = so * tanhf(c);
        g_c[b * H + tid] = c;
        sh[tid] = hn;
        float hp = __shfl_xor_sync(0xffffffffu, hn, 1);
        if (!(tid & 1)) {
            unsigned lo, hi = packhl(hn, hp, lo);
            *(unsigned*)&g_xhH[b * KX + 1024 + tid] = hi;
            *(unsigned*)&g_xhL[b * KX + 1024 + tid] = lo;
            *(unsigned*)&g_histH[((t - 1) * B + b) * HE + tid] = hi;
            *(unsigned*)&g_histL[((t - 1) * B + b) * HE + tid] = lo;
        }
    }
    if (t >= T) return;

    // ---- dec projection: 64 a-quads x 8 k-splits, float4 loads ----
    if (t > 0) {
        __syncthreads();
        int aq = tid & 63, ks = tid >> 6;          // aq: a-quad, ks: k-split
        const float* wp = &Wdec[(ks * 64) * A + 4 * aq];
        const float* hp = &sh[ks * 64];
        float4 acc4 = make_float4(0.f, 0.f, 0.f, 0.f);
#pragma unroll 8
        for (int k = 0; k < 64; k++) {
            float hv = hp[k];
            float4 w = *(const float4*)&wp[k * A];
            acc4.x += hv * w.x; acc4.y += hv * w.y;
            acc4.z += hv * w.z; acc4.w += hv * w.w;
        }
        sred4[tid] = acc4;
        __syncthreads();
        if (tid < 64) {
            float4 s0 = sred4[tid];
#pragma unroll
            for (int ks2 = 1; ks2 < 8; ks2++) {
                float4 p = sred4[ks2 * 64 + tid];
                s0.x += p.x; s0.y += p.y; s0.z += p.z; s0.w += p.w;
            }
            float4 ba = *(const float4*)&b_att[4 * tid];
            s0.x += ba.x; s0.y += ba.y; s0.z += ba.z; s0.w += ba.w;
            *(float4*)&sh_dec[4 * tid] = s0;
        }
    } else {
        if (tid < A) sh_dec[tid] = b_att[tid];
    }

    // ---- prep: zero gates (for GEMM atomics), v_att, xemb pack ----
    *(float4*)&g_gates[b * G4 + tid * 4] = make_float4(0.f, 0.f, 0.f, 0.f);
    if (tid < A) sh_v[tid] = v_att[tid];
    {
        int tok = (t == 0) ? 0 : tgt[b * T + (t - 1)];
        float xe = emb[tok * H + tid];
        float xep = __shfl_xor_sync(0xffffffffu, xe, 1);
        if (!(tid & 1)) {
            unsigned lo, hi = packhl(xe, xep, lo);
            *(unsigned*)&g_xhH[b * KX + tid] = hi;
            *(unsigned*)&g_xhL[b * KX + tid] = lo;
        }
    }
    __syncthreads();

    // ---- scores: 2-row interleave per warp (dual load/MUFU chains) ----
#pragma unroll
    for (int r = 0; r < 4; r++) {
        int s0 = wid * 8 + 2 * r;
        const float* ep0 = &g_enc_proj[(b * S + s0) * A];
        const float* ep1 = ep0 + A;
        float p0 = 0.f, p1 = 0.f;
#pragma unroll
        for (int q = 0; q < 8; q++) {
            int a = lane + 32 * q;
            float d = sh_dec[a], vv = sh_v[a];
            float e0 = ep0[a], e1 = ep1[a];
            p0 += fast_tanh(e0 + d) * vv;
            p1 += fast_tanh(e1 + d) * vv;
        }
#pragma unroll
        for (int off = 16; off; off >>= 1) {
            p0 += __shfl_down_sync(0xffffffffu, p0, off);
            p1 += __shfl_down_sync(0xffffffffu, p1, off);
        }
        if (lane == 0) { sw[s0] = p0; sw[s0 + 1] = p1; }
    }
    __syncthreads();
    if (tid < 32) {
        float m = fmaxf(fmaxf(sw[tid], sw[tid + 32]), fmaxf(sw[tid + 64], sw[tid + 96]));
#pragma unroll
        for (int off = 16; off; off >>= 1) m = fmaxf(m, __shfl_xor_sync(0xffffffffu, m, off));
        if (tid == 0) sredv = m;
    }
    __syncthreads();
    float mx = sredv;
    if (tid < S) sw[tid] = expf(sw[tid] - mx);
    __syncthreads();
    if (tid < 32) {
        float ssum = sw[tid] + sw[tid + 32] + sw[tid + 64] + sw[tid + 96];
#pragma unroll
        for (int off = 16; off; off >>= 1) ssum += __shfl_xor_sync(0xffffffffu, ssum, off);
        if (tid == 0) sredv = 1.f / ssum;
    }
    __syncthreads();
    float rinv = sredv;

    // ---- context: 4 independent accumulator chains over s-quarters ----
    float a0 = 0.f, a1 = 0.f, a2 = 0.f, a3 = 0.f;
    const float* eb = &enc[b * S * E + tid];
#pragma unroll 8
    for (int s = 0; s < 32; s++) {
        a0 += sw[s]      * eb[s * E];
        a1 += sw[s + 32] * eb[(s + 32) * E];
        a2 += sw[s + 64] * eb[(s + 64) * E];
        a3 += sw[s + 96] * eb[(s + 96) * E];
    }
    float v = (a0 + a1 + a2 + a3) * rinv;
    float vp = __shfl_xor_sync(0xffffffffu, v, 1);
    if (!(tid & 1)) {
        unsigned lo, hi = packhl(v, vp, lo);
        *(unsigned*)&g_xhH[b * KX + 512 + tid] = hi;
        *(unsigned*)&g_xhL[b * KX + 512 + tid] = lo;
        *(unsigned*)&g_histH[(t * B + b) * HE + H + tid] = hi;
        *(unsigned*)&g_histL[(t * B + b) * HE + H + tid] = lo;
    }
}

// ---------------- gates GEMM: cp.async double-buffered, split-K=8 ----------
#define MG_STG 15360
__global__ void __launch_bounds__(256) k_mg() {
    extern __shared__ __align__(16) unsigned short dsm[];
    int tid = threadIdx.x, warp = tid >> 5, lane = tid & 31;
    int N0 = blockIdx.x * 128;
    int wr = warp >> 2, wc = warp & 3;
    unsigned sb = smem_u32(dsm);
    float acc[2][4][4];
#pragma unroll
    for (int i = 0; i < 2; i++)
#pragma unroll
        for (int j = 0; j < 4; j++)
#pragma unroll
            for (int q = 0; q < 4; q++) acc[i][j][q] = 0.f;

    int cr = tid >> 1, ch = (tid & 1) * 16;
    auto load_stage = [&](int kc, int st) {
        int k0 = kc * 32;
        unsigned base = sb + st * (MG_STG * 2);
        if (tid < 128) {
            const unsigned short* pa = g_xhH + cr * KX + k0 + ch;
            const unsigned short* pl = g_xhL + cr * KX + k0 + ch;
            unsigned so = base + (cr * PADK + ch) * 2;
            cpa16(so, pa);             cpa16(so + 16, pa + 8);
            cpa16(so + 2560 * 2, pl);  cpa16(so + 2560 * 2 + 16, pl + 8);
        }
        {
            const unsigned short* pb = g_WgH + (size_t)(N0 + cr) * KX + k0 + ch;
            const unsigned short* pbl= g_WgL + (size_t)(N0 + cr) * KX + k0 + ch;
            unsigned so = base + (5120 + cr * PADK + ch) * 2;
            cpa16(so, pb);             cpa16(so + 16, pb + 8);
            cpa16(so + 5120 * 2, pbl); cpa16(so + 5120 * 2 + 16, pbl + 8);
        }
        CP_COMMIT();
    };

    int kc0 = blockIdx.y;
    load_stage(kc0, 0);
    int st = 0;
    for (int kc = kc0; kc < KX / 32; kc += 8) {
        if (kc + 8 < KX / 32) { load_stage(kc + 8, st ^ 1); CP_WAIT1(); }
        else CP_WAIT0();
        __syncthreads();
        unsigned short* sAh = dsm + st * MG_STG;
        unsigned short* sAl = sAh + 2560;
        unsigned short* sBh = sAh + 5120;
        unsigned short* sBl = sAh + 10240;
#pragma unroll
        for (int kq = 0; kq < 2; kq++) {
            int kb = kq * 16 + (lane & 3) * 2;
            uint32_t ah[2][4], al[2][4], bh[4][2], bl[4][2];
#pragma unroll
            for (int mf = 0; mf < 2; mf++) {
                int r = wr * 32 + mf * 16 + (lane >> 2);
                ah[mf][0] = *(const uint32_t*)&sAh[r * PADK + kb];
                ah[mf][1] = *(const uint32_t*)&sAh[(r + 8) * PADK + kb];
                ah[mf][2] = *(const uint32_t*)&sAh[r * PADK + kb + 8];
                ah[mf][3] = *(const uint32_t*)&sAh[(r + 8) * PADK + kb + 8];
                al[mf][0] = *(const uint32_t*)&sAl[r * PADK + kb];
                al[mf][1] = *(const uint32_t*)&sAl[(r + 8) * PADK + kb];
                al[mf][2] = *(const uint32_t*)&sAl[r * PADK + kb + 8];
                al[mf][3] = *(const uint32_t*)&sAl[(r + 8) * PADK + kb + 8];
            }
#pragma unroll
            for (int nf = 0; nf < 4; nf++) {
                int r = wc * 32 + nf * 8 + (lane >> 2);
                bh[nf][0] = *(const uint32_t*)&sBh[r * PADK + kb];
                bh[nf][1] = *(const uint32_t*)&sBh[r * PADK + kb + 8];
                bl[nf][0] = *(const uint32_t*)&sBl[r * PADK + kb];
                bl[nf][1] = *(const uint32_t*)&sBl[r * PADK + kb + 8];
            }
#pragma unroll
            for (int mf = 0; mf < 2; mf++)
#pragma unroll
                for (int nf = 0; nf < 4; nf++) {
                    mma16816(acc[mf][nf], ah[mf][0], ah[mf][1], ah[mf][2], ah[mf][3],
                             bh[nf][0], bh[nf][1]);
                    mma16816(acc[mf][nf], al[mf][0], al[mf][1], al[mf][2], al[mf][3],
                             bh[nf][0], bh[nf][1]);
                    mma16816(acc[mf][nf], ah[mf][0], ah[mf][1], ah[mf][2], ah[mf][3],
                             bl[nf][0], bl[nf][1]);
                }
        }
        __syncthreads();
        st ^= 1;
    }
#pragma unroll
    for (int mf = 0; mf < 2; mf++) {
        int m = wr * 32 + mf * 16 + (lane >> 2);
#pragma unroll
        for (int nf = 0; nf < 4; nf++) {
            int n = N0 + wc * 32 + nf * 8 + (lane & 3) * 2;
            atomicAdd(&g_gates[m * G4 + n],           acc[mf][nf][0]);
            atomicAdd(&g_gates[m * G4 + n + 1],       acc[mf][nf][1]);
            atomicAdd(&g_gates[(m + 8) * G4 + n],     acc[mf][nf][2]);
            atomicAdd(&g_gates[(m + 8) * G4 + n + 1], acc[mf][nf][3]);
        }
    }
}

// ---------------- 128x128 mma GEMM, cp.async double-buffered ---------------
#define MM_STG 20480
__global__ void __launch_bounds__(256) k_mma128(
    const unsigned short* __restrict__ Ahg, const unsigned short* __restrict__ Alg,
    const unsigned short* __restrict__ Bhg, const unsigned short* __restrict__ Blg,
    int ldk, int nkc, const float* __restrict__ bias,
    float* __restrict__ out, int ldc, int perm)
{
    extern __shared__ __align__(16) unsigned short dsm[];
    int tid = threadIdx.x, warp = tid >> 5, lane = tid & 31;
    int N0 = blockIdx.x * 128, M0 = blockIdx.y * 128;
    int wr = warp >> 2, wc = warp & 3;
    unsigned sb = smem_u32(dsm);
    float acc[4][4][4];
#pragma unroll
    for (int i = 0; i < 4; i++)
#pragma unroll
        for (int j = 0; j < 4; j++)
#pragma unroll
            for (int q = 0; q < 4; q++) acc[i][j][q] = 0.f;

    int cr = tid >> 1, ch = (tid & 1) * 16;
    auto load_stage = [&](int kc, int st) {
        int k0 = kc * 32;
        unsigned base = sb + st * (MM_STG * 2);
        unsigned so = base + (cr * PADK + ch) * 2;
        const unsigned short* pa = Ahg + (size_t)(M0 + cr) * ldk + k0 + ch;
        const unsigned short* pl = Alg + (size_t)(M0 + cr) * ldk + k0 + ch;
        const unsigned short* pb = Bhg + (size_t)(N0 + cr) * ldk + k0 + ch;
        const unsigned short* pbl= Blg + (size_t)(N0 + cr) * ldk + k0 + ch;
        cpa16(so, pa);                  cpa16(so + 16, pa + 8);
        cpa16(so + 5120 * 2, pl);       cpa16(so + 5120 * 2 + 16, pl + 8);
        cpa16(so + 10240 * 2, pb);      cpa16(so + 10240 * 2 + 16, pb + 8);
        cpa16(so + 15360 * 2, pbl);     cpa16(so + 15360 * 2 + 16, pbl + 8);
        CP_COMMIT();
    };

    load_stage(0, 0);
    int st = 0;
    for (int kc = 0; kc < nkc; kc++) {
        if (kc + 1 < nkc) { load_stage(kc + 1, st ^ 1); CP_WAIT1(); }
        else CP_WAIT0();
        __syncthreads();
        unsigned short* sAh = dsm + st * MM_STG;
        unsigned short* sAl = sAh + 5120;
        unsigned short* sBh = sAh + 10240;
        unsigned short* sBl = sAh + 15360;
#pragma unroll
        for (int kq = 0; kq < 2; kq++) {
            int kb = kq * 16 + (lane & 3) * 2;
            uint32_t ah[4][4], al[4][4], bh[4][2], bl[4][2];
            int ar = wr * 64 + (lane >> 2);
#pragma unroll
            for (int mf = 0; mf < 4; mf++) {
                int r = ar + mf * 16;
                ah[mf][0] = *(const uint32_t*)&sAh[r * PADK + kb];
                ah[mf][1] = *(const uint32_t*)&sAh[(r + 8) * PADK + kb];
                ah[mf][2] = *(const uint32_t*)&sAh[r * PADK + kb + 8];
                ah[mf][3] = *(const uint32_t*)&sAh[(r + 8) * PADK + kb + 8];
                al[mf][0] = *(const uint32_t*)&sAl[r * PADK + kb];
                al[mf][1] = *(const uint32_t*)&sAl[(r + 8) * PADK + kb];
                al[mf][2] = *(const uint32_t*)&sAl[r * PADK + kb + 8];
                al[mf][3] = *(const uint32_t*)&sAl[(r + 8) * PADK + kb + 8];
            }
            int br = wc * 32 + (lane >> 2);
#pragma unroll
            for (int nf = 0; nf < 4; nf++) {
                int r = br + nf * 8;
                bh[nf][0] = *(const uint32_t*)&sBh[r * PADK + kb];
                bh[nf][1] = *(const uint32_t*)&sBh[r * PADK + kb + 8];
                bl[nf][0] = *(const uint32_t*)&sBl[r * PADK + kb];
                bl[nf][1] = *(const uint32_t*)&sBl[r * PADK + kb + 8];
            }
#pragma unroll
            for (int mf = 0; mf < 4; mf++)
#pragma unroll
                for (int nf = 0; nf < 4; nf++) {
                    mma16816(acc[mf][nf], ah[mf][0], ah[mf][1], ah[mf][2], ah[mf][3],
                             bh[nf][0], bh[nf][1]);
                    mma16816(acc[mf][nf], al[mf][0], al[mf][1], al[mf][2], al[mf][3],
                             bh[nf][0], bh[nf][1]);
                    mma16816(acc[mf][nf], ah[mf][0], ah[mf][1], ah[mf][2], ah[mf][3],
                             bl[nf][0], bl[nf][1]);
                }
        }
        __syncthreads();
        st ^= 1;
    }
#pragma unroll
    for (int mf = 0; mf < 4; mf++) {
        int m0g = M0 + wr * 64 + mf * 16 + (lane >> 2);
#pragma unroll
        for (int nf = 0; nf < 4; nf++) {
            int n = N0 + wc * 32 + nf * 8 + (lane & 3) * 2;
            float2 bia = bias ? *(const float2*)&bias[n] : make_float2(0.f, 0.f);
            int m1 = m0g + 8;
            int r0 = perm ? ((m0g & 63) * T + (m0g >> 6)) : m0g;
            int r1 = perm ? ((m1 & 63) * T + (m1 >> 6)) : m1;
            float2 v0 = make_float2(acc[mf][nf][0] + bia.x, acc[mf][nf][1] + bia.y);
            float2 v1 = make_float2(acc[mf][nf][2] + bia.x, acc[mf][nf][3] + bia.y);
            *(float2*)&out[(size_t)r0 * ldc + n] = v0;
            *(float2*)&out[(size_t)r1 * ldc + n] = v1;
        }
    }
}

// ---------------- launch ----------------------------------------------------
extern "C" void kernel_launch(void* const* d_in, const int* in_sizes, int n_in,
                              void* d_out, int out_size) {
    const float* enc  = (const float*)d_in[0];
    const int*   tgt  = (const int*)  d_in[1];
    const float* emb  = (const float*)d_in[2];
    const float* Wenc = (const float*)d_in[3];
    const float* Wdec = (const float*)d_in[4];
    const float* batt = (const float*)d_in[5];
    const float* vatt = (const float*)d_in[6];
    const float* Wih  = (const float*)d_in[7];
    const float* Whh  = (const float*)d_in[8];
    const float* bih  = (const float*)d_in[9];
    const float* bhh  = (const float*)d_in[10];
    const float* Wout = (const float*)d_in[11];
    const float* bout = (const float*)d_in[12];
    float* out = (float*)d_out;

    float *encp;
    unsigned short *hH, *hL, *wH, *wL, *eH, *eL, *weH, *weL;
    cudaGetSymbolAddress((void**)&encp, g_enc_proj);
    cudaGetSymbolAddress((void**)&hH, g_histH);
    cudaGetSymbolAddress((void**)&hL, g_histL);
    cudaGetSymbolAddress((void**)&wH, g_WoutH);
    cudaGetSymbolAddress((void**)&wL, g_WoutL);
    cudaGetSymbolAddress((void**)&eH, g_encH);
    cudaGetSymbolAddress((void**)&eL, g_encL);
    cudaGetSymbolAddress((void**)&weH, g_WencH);
    cudaGetSymbolAddress((void**)&weL, g_WencL);

    static int attr_set = 0;
    if (!attr_set) {
        cudaFuncSetAttribute(k_mma128, cudaFuncAttributeMaxDynamicSharedMemorySize,
                             MM_STG * 4);
        cudaFuncSetAttribute(k_mg, cudaFuncAttributeMaxDynamicSharedMemorySize,
                             MG_STG * 4);
        attr_set = 1;
    }

    k_init<<<128, 256>>>(bih, bhh);                                         // 1
    k_pack<<<8192 + 16384 + 256 + 6144, 256>>>(enc, Wout, Wenc, Wih, Whh);  // 2
    k_mma128<<<dim3(A / 128, (B * S) / 128), 256, MM_STG * 4>>>(            // 3
        eH, eL, weH, weL, E, E / 32, nullptr, encp, A, 0);

    for (int t = 0; t < T; t++) {
        k_step<<<B, 512>>>(vatt, enc, batt, Wdec, tgt, emb, t);   // 4 at t=0; 6th launch = t=1 (profiled)
        k_mg<<<dim3(G4 / 128, 8), 256, MG_STG * 4>>>();
    }
    k_step<<<B, 512>>>(vatt, enc, batt, Wdec, tgt, emb, T);

    k_mma128<<<dim3(V / 128, (T * B) / 128), 256, MM_STG * 4>>>(
        hH, hL, wH, wL, HE, HE / 32, bout, out, V, 1);
}